// round 14
// baseline (speedup 1.0000x reference)
#include <cuda_runtime.h>

#define T_LEN  1024
#define NSTEP  1023
#define B_SZ   8192

typedef unsigned long long ull;

// scratch: time-major inputs
__device__ int   g_act_t[T_LEN * B_SZ];            // [t][b]
__device__ float g_rew_t[T_LEN * B_SZ];            // [t][b]

// ---------------- packed f32x2 helpers ----------------
__device__ __forceinline__ void ffma2(ull& d, ull a, ull b) {
    asm("fma.rn.f32x2 %0, %1, %2, %0;" : "+l"(d) : "l"(a), "l"(b));
}
__device__ __forceinline__ ull mul2(ull a, ull b) {
    ull r; asm("mul.rn.f32x2 %0, %1, %2;" : "=l"(r) : "l"(a), "l"(b)); return r;
}
__device__ __forceinline__ ull add2(ull a, ull b) {
    ull r; asm("add.rn.f32x2 %0, %1, %2;" : "=l"(r) : "l"(a), "l"(b)); return r;
}
__device__ __forceinline__ ull pack2(float x, float y) {
    ull r; asm("mov.b64 %0, {%1, %2};" : "=l"(r) : "f"(x), "f"(y)); return r;
}
__device__ __forceinline__ float2 unpack2(ull v) {
    float2 r; asm("mov.b64 {%0, %1}, %2;" : "=f"(r.x), "=f"(r.y) : "l"(v)); return r;
}
__device__ __forceinline__ ull shflx64(ull v, int m) {
    return __shfl_xor_sync(0xFFFFFFFFu, v, m);
}
// input pre-scaled by 2*log2(e):  tanh = 1 - 2/(2^x' + 1)   (~1e-6 abs err)
__device__ __forceinline__ float tanh_pre(float xs) {
    float e, r;
    asm("ex2.approx.f32 %0, %1;" : "=f"(e) : "f"(xs));
    asm("rcp.approx.f32 %0, %1;" : "=f"(r) : "f"(e + 1.0f));
    return fmaf(-2.0f, r, 1.0f);
}
#define TANH_SC 2.8853900817779268f   // 2*log2(e)

// ---------------- transpose [B][T] -> [T][B]  +  zero(out) ----------------
__global__ void __launch_bounds__(256)
transpose_kernel(const int* __restrict__ act, const float* __restrict__ rew,
                 float* __restrict__ out) {
    const int tx = threadIdx.x, ty = threadIdx.y;
    if (blockIdx.z == 2) {
        const size_t base =
            ((size_t)blockIdx.y * gridDim.x + blockIdx.x) * (size_t)NSTEP;
        float4* o4 = (float4*)out;
        const float4 z = make_float4(0.f, 0.f, 0.f, 0.f);
        const int tid = ty * 32 + tx;
        for (int i = tid; i < NSTEP; i += 256) o4[base + i] = z;
        return;
    }
    __shared__ unsigned tile[32][33];
    const int tt = blockIdx.x * 32, tb = blockIdx.y * 32;
    const unsigned* src = (blockIdx.z == 0) ? (const unsigned*)act : (const unsigned*)rew;
    unsigned*       dst = (blockIdx.z == 0) ? (unsigned*)g_act_t  : (unsigned*)g_rew_t;
    #pragma unroll
    for (int i = 0; i < 32; i += 8)
        tile[ty + i][tx] = src[(long long)(tb + ty + i) * T_LEN + tt + tx];
    __syncthreads();
    #pragma unroll
    for (int i = 0; i < 32; i += 8)
        dst[(long long)(tt + ty + i) * B_SZ + tb + tx] = tile[tx][ty + i];
}

// ---------------- main recurrent kernel ----------------
// 4-LANE SPLIT, register state, shuffle gather, barrier-free.
// grid = 256 CTAs x 256 thr (8 warps, wid%4-balanced). CTAs 0..127: reward;
// 128..255: action. Warp owns 8 elements; lane ll of element e owns rows/dims
// [8ll, 8ll+8). Own state: s[4] (f32x2). Full 32-dim state rebuilt per step by
// a 2-round xor butterfly into LANE-RELATIVE segment order [ll,ll^1,ll^2,ll^3];
// first-layer weights pre-permuted per-ll to match. Butterfly issued at step
// END so SHFL latency hides under the (independent) second-layer epilogue.
// Outputs: 1 atomicAdd per lane per step into the pre-zeroed out buffer.
__global__ void __launch_bounds__(256)
memann_mod(const float* __restrict__ w_r1, const float* __restrict__ b_r1,
           const float* __restrict__ w_r2, const float* __restrict__ b_r2,
           const float* __restrict__ w_a1, const float* __restrict__ b_a1,
           const float* __restrict__ w_a2, const float* __restrict__ b_a2,
           float*       __restrict__ out)
{
    // ll-stride 130 ull = 1040B -> 4 lane addresses 16B apart mod 128:
    // conflict-free broadcast LDS.128.
    __shared__ __align__(16) ull w1p[4][130];     // [ll][r*16 + p], prescaled
    // action one-hot bias (prescaled): [ll][a][rp] = {row, row+1}, row=8ll+2rp
    __shared__ __align__(16) ull colba[4][4][4];
    __shared__ float sc[5];                        // b_r2, b_a2[0..3]

    const int tid = threadIdx.x;
    const bool is_rew = blockIdx.x < 128;

    // ---- one-time staging (pre-permuted per ll) ----
    if (is_rew) {
        #pragma unroll
        for (int k = 0; k < 2; k++) {
            const int i = tid * 2 + k;             // 512 ull
            const int ll = i >> 7, r = (i >> 4) & 7, p = i & 15;
            const int seg = p >> 2, u = p & 3;
            const int gcol = 8 * (ll ^ seg) + 2 * u;
            const int row  = 8 * ll + r;
            w1p[ll][r * 16 + p] = pack2(w_r1[row * 33 + 1 + gcol] * TANH_SC,
                                        w_r1[row * 33 + 2 + gcol] * TANH_SC);
        }
        if (tid == 0) sc[0] = b_r2[0];
    } else {
        #pragma unroll
        for (int k = 0; k < 2; k++) {
            const int i = tid * 2 + k;
            const int ll = i >> 7, r = (i >> 4) & 7, p = i & 15;
            const int seg = p >> 2, u = p & 3;
            const int gcol = 8 * (ll ^ seg) + 2 * u;
            const int row  = 8 * ll + r;
            w1p[ll][r * 16 + p] = pack2(w_a1[row * 36 + 4 + gcol] * TANH_SC,
                                        w_a1[row * 36 + 5 + gcol] * TANH_SC);
        }
        if (tid < 64) {
            const int ll = tid >> 4, a = (tid >> 2) & 3, rp = tid & 3;
            const int row = 8 * ll + 2 * rp;
            colba[ll][a][rp] =
                pack2((w_a1[row * 36 + a] + b_a1[row]) * TANH_SC,
                      (w_a1[(row + 1) * 36 + a] + b_a1[row + 1]) * TANH_SC);
        }
        if (tid >= 64 && tid < 68) sc[1 + tid - 64] = b_a2[tid - 64];
    }
    __syncthreads();

    const int lane = tid & 31, wid = tid >> 5;
    const int eg = lane >> 2;           // element within warp (0..7)
    const int ll = lane & 3;            // sub-lane: rows/dims [8ll, 8ll+8)
    const long long b =
        (long long)(is_rew ? blockIdx.x : blockIdx.x - 128) * 64 + wid * 8 + eg;
    const int*   ap = g_act_t + b;
    const float* rp = g_rew_t + b;
    float* op = out + ((size_t)b * NSTEP) * 4 + ll;   // this lane's output slot

    ull fullv[16];                      // gathered prev state, lane-relative
    #pragma unroll
    for (int p = 0; p < 16; p++) fullv[p] = 0ull;

    if (is_rew) {
        // ---------------- reward module ----------------
        ull bw[8], w2s[4];
        #pragma unroll
        for (int r = 0; r < 8; r++) {
            const int row = 8 * ll + r;
            bw[r] = pack2(b_r1[row] * TANH_SC, w_r1[row * 33] * TANH_SC);
        }
        #pragma unroll
        for (int u = 0; u < 4; u++)
            w2s[u] = pack2(w_r2[8 * ll + 2 * u], w_r2[8 * ll + 2 * u + 1]);
        const float br2 = sc[0];
        float q = 0.0f;

        int   a_cur = ap[0];
        float r_cur = rp[0];
        for (int t = 0; t < NSTEP; t++) {
            const int   a_nxt = ap[(t + 1) * B_SZ];
            const float r_nxt = rp[(t + 1) * B_SZ];

            const ull rv = pack2(1.0f, r_cur);
            ull acc[8];
            #pragma unroll
            for (int r = 0; r < 8; r++) acc[r] = mul2(bw[r], rv);  // {b', w0'*r}
            #pragma unroll
            for (int pp = 0; pp < 8; pp++) {
                #pragma unroll
                for (int r = 0; r < 8; r++) {
                    const ulonglong2 w = *(const ulonglong2*)&w1p[ll][r * 16 + 2 * pp];
                    ffma2(acc[r], w.x, fullv[2 * pp]);
                    ffma2(acc[r], w.y, fullv[2 * pp + 1]);
                }
            }
            float sn[8];
            #pragma unroll
            for (int r = 0; r < 8; r++) {
                const float2 u = unpack2(acc[r]);
                sn[r] = tanh_pre(u.x + u.y);
            }
            ull s[4];
            #pragma unroll
            for (int u = 0; u < 4; u++) s[u] = pack2(sn[2 * u], sn[2 * u + 1]);

            // butterfly gather for NEXT step (latency hidden by epilogue below)
            #pragma unroll
            for (int u = 0; u < 4; u++) fullv[u] = s[u];
            #pragma unroll
            for (int u = 0; u < 4; u++) fullv[4 + u] = shflx64(s[u], 1);
            #pragma unroll
            for (int u = 0; u < 8; u++) fullv[8 + u] = shflx64(fullv[u], 2);

            // q_new: own-8-dims partial + 4-lane butterfly reduce
            ull qa = 0ull;
            #pragma unroll
            for (int u = 0; u < 4; u++) ffma2(qa, w2s[u], s[u]);
            const float2 qf = unpack2(qa);
            float qs = qf.x + qf.y;
            qs += __shfl_xor_sync(0xFFFFFFFFu, qs, 1);
            qs += __shfl_xor_sync(0xFFFFFFFFu, qs, 2);
            const float q_new = qs + br2;

            q = (a_cur == ll) ? q_new : q * 0.95f;
            atomicAdd(op + (size_t)t * 4, q);

            a_cur = a_nxt; r_cur = r_nxt;
        }
    } else {
        // ---------------- action-history module ----------------
        ull w2a[4][4];
        #pragma unroll
        for (int k = 0; k < 4; k++)
            #pragma unroll
            for (int u = 0; u < 4; u++)
                w2a[k][u] = pack2(w_a2[k * 32 + 8 * ll + 2 * u],
                                  w_a2[k * 32 + 8 * ll + 2 * u + 1]);
        const float ba = sc[1 + ll];

        int a_cur = ap[0];
        for (int t = 0; t < NSTEP; t++) {
            const int a_nxt = ap[(t + 1) * B_SZ];

            // one-hot bias init (a_cur known since previous step)
            const ulonglong2 cbA = *(const ulonglong2*)&colba[ll][a_cur][0];
            const ulonglong2 cbB = *(const ulonglong2*)&colba[ll][a_cur][2];
            ull acc[8];
            acc[0] = cbA.x; acc[1] = 0ull; acc[2] = cbA.y; acc[3] = 0ull;
            acc[4] = cbB.x; acc[5] = 0ull; acc[6] = cbB.y; acc[7] = 0ull;
            // repack: colba pair {row,row+1} maps to acc[2rp] scalar-pair; keep
            // layout: acc[r] accumulates {partial_a, partial_b}; bias for row r
            // is the r-th scalar -> place {bias_2rp, bias_2rp+1} split:
            #pragma unroll
            for (int rp2 = 0; rp2 < 4; rp2++) {
                const ull cb = (rp2 < 2) ? ((rp2 == 0) ? cbA.x : cbA.y)
                                         : ((rp2 == 2) ? cbB.x : cbB.y);
                const float2 c2 = unpack2(cb);
                acc[2 * rp2]     = pack2(c2.x, 0.0f);
                acc[2 * rp2 + 1] = pack2(c2.y, 0.0f);
            }
            #pragma unroll
            for (int pp = 0; pp < 8; pp++) {
                #pragma unroll
                for (int r = 0; r < 8; r++) {
                    const ulonglong2 w = *(const ulonglong2*)&w1p[ll][r * 16 + 2 * pp];
                    ffma2(acc[r], w.x, fullv[2 * pp]);
                    ffma2(acc[r], w.y, fullv[2 * pp + 1]);
                }
            }
            float sn[8];
            #pragma unroll
            for (int r = 0; r < 8; r++) {
                const float2 u = unpack2(acc[r]);
                sn[r] = tanh_pre(u.x + u.y);
            }
            ull s[4];
            #pragma unroll
            for (int u = 0; u < 4; u++) s[u] = pack2(sn[2 * u], sn[2 * u + 1]);

            // butterfly gather for NEXT step
            #pragma unroll
            for (int u = 0; u < 4; u++) fullv[u] = s[u];
            #pragma unroll
            for (int u = 0; u < 4; u++) fullv[4 + u] = shflx64(s[u], 1);
            #pragma unroll
            for (int u = 0; u < 8; u++) fullv[8 + u] = shflx64(fullv[u], 2);

            // c_k partials over own 8 dims, packed 4-lane reduce
            ull ca0 = 0ull, ca1 = 0ull, ca2 = 0ull, ca3 = 0ull;
            #pragma unroll
            for (int u = 0; u < 4; u++) {
                ffma2(ca0, w2a[0][u], s[u]);
                ffma2(ca1, w2a[1][u], s[u]);
                ffma2(ca2, w2a[2][u], s[u]);
                ffma2(ca3, w2a[3][u], s[u]);
            }
            const float2 f0 = unpack2(ca0), f1 = unpack2(ca1);
            const float2 f2 = unpack2(ca2), f3 = unpack2(ca3);
            ull v01 = pack2(f0.x + f0.y, f1.x + f1.y);
            ull v23 = pack2(f2.x + f2.y, f3.x + f3.y);
            v01 = add2(v01, shflx64(v01, 1));
            v23 = add2(v23, shflx64(v23, 1));
            v01 = add2(v01, shflx64(v01, 2));
            v23 = add2(v23, shflx64(v23, 2));
            const ull    vsel = (ll & 2) ? v23 : v01;
            const float2 vv   = unpack2(vsel);
            atomicAdd(op + (size_t)t * 4, ((ll & 1) ? vv.y : vv.x) + ba);

            a_cur = a_nxt;
        }
    }
}

extern "C" void kernel_launch(void* const* d_in, const int* in_sizes, int n_in,
                              void* d_out, int out_size) {
    (void)in_sizes; (void)n_in; (void)out_size;
    transpose_kernel<<<dim3(T_LEN / 32, B_SZ / 32, 3), dim3(32, 8)>>>(
        (const int*)d_in[0], (const float*)d_in[1], (float*)d_out);
    memann_mod<<<256, 256>>>(
        (const float*)d_in[2], (const float*)d_in[3],
        (const float*)d_in[4], (const float*)d_in[5],
        (const float*)d_in[6], (const float*)d_in[7],
        (const float*)d_in[8], (const float*)d_in[9],
        (float*)d_out);
}

// round 15
// speedup vs baseline: 2.1048x; 2.1048x over previous
#include <cuda_runtime.h>

#define T_LEN  1024
#define NSTEP  1023
#define B_SZ   8192

typedef unsigned long long ull;

// scratch: time-major inputs
__device__ int   g_act_t[T_LEN * B_SZ];            // [t][b]
__device__ float g_rew_t[T_LEN * B_SZ];            // [t][b]

// ---------------- packed f32x2 helpers ----------------
__device__ __forceinline__ void ffma2(ull& d, ull a, ull b) {
    asm("fma.rn.f32x2 %0, %1, %2, %0;" : "+l"(d) : "l"(a), "l"(b));
}
__device__ __forceinline__ ull mul2(ull a, ull b) {
    ull r; asm("mul.rn.f32x2 %0, %1, %2;" : "=l"(r) : "l"(a), "l"(b)); return r;
}
__device__ __forceinline__ ull pack2(float x, float y) {
    ull r; asm("mov.b64 %0, {%1, %2};" : "=l"(r) : "f"(x), "f"(y)); return r;
}
__device__ __forceinline__ float2 unpack2(ull v) {
    float2 r; asm("mov.b64 {%0, %1}, %2;" : "=f"(r.x), "=f"(r.y) : "l"(v)); return r;
}
__device__ __forceinline__ ull shflx64(ull v, int m) {
    return __shfl_xor_sync(0xFFFFFFFFu, v, m);
}
// input pre-scaled by 2*log2(e):  tanh = 1 - 2/(2^x' + 1)   (~1e-6 abs err)
__device__ __forceinline__ float tanh_pre(float xs) {
    float e, r;
    asm("ex2.approx.f32 %0, %1;" : "=f"(e) : "f"(xs));
    asm("rcp.approx.f32 %0, %1;" : "=f"(r) : "f"(e + 1.0f));
    return fmaf(-2.0f, r, 1.0f);
}
#define TANH_SC 2.8853900817779268f   // 2*log2(e)

// ---------------- transpose [B][T] -> [T][B]  +  zero(out) ----------------
__global__ void __launch_bounds__(256)
transpose_kernel(const int* __restrict__ act, const float* __restrict__ rew,
                 float* __restrict__ out) {
    const int tx = threadIdx.x, ty = threadIdx.y;
    if (blockIdx.z == 2) {
        const size_t base =
            ((size_t)blockIdx.y * gridDim.x + blockIdx.x) * (size_t)NSTEP;
        float4* o4 = (float4*)out;
        const float4 z = make_float4(0.f, 0.f, 0.f, 0.f);
        const int tid = ty * 32 + tx;
        for (int i = tid; i < NSTEP; i += 256) o4[base + i] = z;
        return;
    }
    __shared__ unsigned tile[32][33];
    const int tt = blockIdx.x * 32, tb = blockIdx.y * 32;
    const unsigned* src = (blockIdx.z == 0) ? (const unsigned*)act : (const unsigned*)rew;
    unsigned*       dst = (blockIdx.z == 0) ? (unsigned*)g_act_t  : (unsigned*)g_rew_t;
    #pragma unroll
    for (int i = 0; i < 32; i += 8)
        tile[ty + i][tx] = src[(long long)(tb + ty + i) * T_LEN + tt + tx];
    __syncthreads();
    #pragma unroll
    for (int i = 0; i < 32; i += 8)
        dst[(long long)(tt + ty + i) * B_SZ + tb + tx] = tile[tx][ty + i];
}

// ---------------- main recurrent kernel ----------------
// Champion R11 geometry (128 CTAs x 256 thr; 2 lanes/element; pipelined
// epilogue; atomic RED outputs) + LSU wavefront diet:
//  (1) 8 loop-invariant weight ulonglong2 (m4=0 own-half ppo 0-1) hoisted to
//      registers in both branches,
//  (2) action one-hot bias relayout [h][m4][a][4] so the per-element a_cur
//      gather spans 64B instead of 512B.
__global__ void __launch_bounds__(256, 1)
memann_mod(const float* __restrict__ w_r1, const float* __restrict__ b_r1,
           const float* __restrict__ w_r2, const float* __restrict__ b_r2,
           const float* __restrict__ w_a1, const float* __restrict__ b_a1,
           const float* __restrict__ w_a2, const float* __restrict__ b_a2,
           float*       __restrict__ out)
{
    __shared__ __align__(16) ulonglong2 wrk[16][8][2];  // [m][pp][h]: row h*16+m
    __shared__ __align__(16) ulonglong2 wak[16][8][2];
    __shared__ __align__(16) ull  bw1s[16][2];          // {b_r1', w_r1[.,0]'}
    __shared__ __align__(16) ull  wr2n[2][16];          // [h][pp]: own-half-first
    __shared__ __align__(16) ull  wa2n[2][2][16];       // [h][k2][pp]: k=2h+k2
    __shared__ __align__(16) float colb2[2][4][4][4];   // [h][m4][a][mm]
    __shared__ float sc[5];                              // b_r2, b_a2[0..3]

    const int tid = threadIdx.x;
    const bool is_reward = blockIdx.x < 64;

    // ---- staging ----
    if (is_reward) {
        #pragma unroll
        for (int k = 0; k < 2; k++) {
            int idx = tid * 2 + k;                 // 512 ull
            int u2 = idx & 1, h = (idx >> 1) & 1, pp = (idx >> 2) & 7, m = idx >> 5;
            int row = h * 16 + m, u = 2 * pp + u2;
            ((ull*)&wrk[m][pp][h])[u2] =
                pack2(w_r1[row * 33 + 1 + 2 * u] * TANH_SC,
                      w_r1[row * 33 + 2 + 2 * u] * TANH_SC);
        }
        if (tid < 32) {
            int h = tid >> 4, m = tid & 15;
            int row = h * 16 + m;
            bw1s[m][h] = pack2(b_r1[row] * TANH_SC, w_r1[row * 33] * TANH_SC);
        }
        if (tid >= 64 && tid < 96) {               // wr2n: own-half-first layout
            int h = (tid - 64) >> 4, pp = (tid - 64) & 15;
            int d = (pp < 8) ? 16 * h + 2 * pp : 16 * (1 - h) + 2 * (pp - 8);
            wr2n[h][pp] = pack2(w_r2[d], w_r2[d + 1]);
        }
        if (tid == 96) sc[0] = b_r2[0];
    } else {
        #pragma unroll
        for (int k = 0; k < 2; k++) {
            int idx = tid * 2 + k;
            int u2 = idx & 1, h = (idx >> 1) & 1, pp = (idx >> 2) & 7, m = idx >> 5;
            int row = h * 16 + m, u = 2 * pp + u2;
            ((ull*)&wak[m][pp][h])[u2] =
                pack2(w_a1[row * 36 + 4 + 2 * u] * TANH_SC,
                      w_a1[row * 36 + 5 + 2 * u] * TANH_SC);
        }
        if (tid < 128) {                           // colb2[h][m4][a][mm]
            int h = tid >> 6, m4 = (tid >> 4) & 3, a = (tid >> 2) & 3, mm = tid & 3;
            int row = h * 16 + m4 * 4 + mm;
            colb2[h][m4][a][mm] = (w_a1[row * 36 + a] + b_a1[row]) * TANH_SC;
        }
        if (tid >= 128 && tid < 192) {             // wa2n: rows k=2h+k2, own-first
            int idx = tid - 128;
            int h = idx >> 5, k2 = (idx >> 4) & 1, pp = idx & 15;
            int kk = 2 * h + k2;
            int d = (pp < 8) ? 16 * h + 2 * pp : 16 * (1 - h) + 2 * (pp - 8);
            wa2n[h][k2][pp] = pack2(w_a2[kk * 32 + d], w_a2[kk * 32 + d + 1]);
        }
        if (tid >= 192 && tid < 196) sc[1 + tid - 192] = b_a2[tid - 192];
    }
    __syncthreads();

    const int lane = tid & 31, wid = tid >> 5;
    const int h  = lane & 1;
    const int el = lane >> 1;
    const int cta_mod = is_reward ? blockIdx.x : blockIdx.x - 64;
    const long long b = (long long)cta_mod * 128 + wid * 16 + el;
    const int*   ap = g_act_t + b;
    const float* rp = g_rew_t + b;

    ull sh[8];
    #pragma unroll
    for (int u = 0; u < 8; u++) sh[u] = 0ull;

    float* op = out + (b * NSTEP) * 4 + 2 * h;   // this lane's 2 output slots

    if (is_reward) {
        ull bi[16];
        #pragma unroll
        for (int m = 0; m < 16; m++) bi[m] = bw1s[m][h];
        ull w2f[16];                               // full w_r2, own-half-first
        #pragma unroll
        for (int pp = 0; pp < 16; pp++) w2f[pp] = wr2n[h][pp];
        // hoisted weights: m4=0 block, own-half ppo 0..1 (8 ulonglong2)
        ulonglong2 wre[4][2];
        #pragma unroll
        for (int mm = 0; mm < 4; mm++)
            #pragma unroll
            for (int ppo = 0; ppo < 2; ppo++)
                wre[mm][ppo] = wrk[mm][h * 4 + ppo][h];
        const float br2 = sc[0];
        const int   kA = 2 * h, kB = 2 * h + 1;
        float qA = 0.f, qB = 0.f;

        int   a_prev = 0;
        int   a_cur  = ap[0];
        float r_cur  = rp[0];
        for (int t = 0; t < NSTEP; t++) {
            const int   a_nxt = ap[(t + 1) * B_SZ];
            const float r_nxt = rp[(t + 1) * B_SZ];
            ull xo[8];
            #pragma unroll
            for (int u = 0; u < 8; u++) xo[u] = shflx64(sh[u], 1);

            // ---- pipelined epilogue: emit output for step t-1 ----
            if (t > 0) {
                ull qa = 0ull;
                #pragma unroll
                for (int pp = 0; pp < 8; pp++) {
                    ffma2(qa, w2f[pp],     sh[pp]);
                    ffma2(qa, w2f[8 + pp], xo[pp]);
                }
                const float2 qf = unpack2(qa);
                const float q_new = qf.x + qf.y + br2;
                qA = (a_prev == kA) ? q_new : qA * 0.95f;
                qB = (a_prev == kB) ? q_new : qB * 0.95f;
                atomicAdd(op + (size_t)(t - 1) * 4,     qA);
                atomicAdd(op + (size_t)(t - 1) * 4 + 1, qB);
            }

            const ull rv = pack2(1.0f, r_cur);
            float sn[16];
            #pragma unroll
            for (int m4 = 0; m4 < 4; m4++) {
                ull acc[4];
                #pragma unroll
                for (int mm = 0; mm < 4; mm++)
                    acc[mm] = mul2(bi[m4 * 4 + mm], rv);   // {b', w0'*r}
                #pragma unroll
                for (int ppo = 0; ppo < 4; ppo++) {         // own half first
                    const int pp = h * 4 + ppo;
                    #pragma unroll
                    for (int mm = 0; mm < 4; mm++) {
                        ulonglong2 w = (m4 == 0 && ppo < 2)
                                     ? wre[mm][ppo]
                                     : wrk[m4 * 4 + mm][pp][h];
                        ffma2(acc[mm], w.x, sh[2 * ppo]);
                        ffma2(acc[mm], w.y, sh[2 * ppo + 1]);
                    }
                }
                #pragma unroll
                for (int ppo = 0; ppo < 4; ppo++) {         // partner half
                    const int pq = (1 - h) * 4 + ppo;
                    #pragma unroll
                    for (int mm = 0; mm < 4; mm++) {
                        ulonglong2 w = wrk[m4 * 4 + mm][pq][h];
                        ffma2(acc[mm], w.x, xo[2 * ppo]);
                        ffma2(acc[mm], w.y, xo[2 * ppo + 1]);
                    }
                }
                #pragma unroll
                for (int mm = 0; mm < 4; mm++) {
                    float2 u = unpack2(acc[mm]);
                    sn[m4 * 4 + mm] = tanh_pre(u.x + u.y);
                }
            }
            #pragma unroll
            for (int u = 0; u < 8; u++) sh[u] = pack2(sn[2 * u], sn[2 * u + 1]);

            a_prev = a_cur; a_cur = a_nxt; r_cur = r_nxt;
        }
        // final epilogue for step NSTEP-1
        {
            ull xo[8];
            #pragma unroll
            for (int u = 0; u < 8; u++) xo[u] = shflx64(sh[u], 1);
            ull qa = 0ull;
            #pragma unroll
            for (int pp = 0; pp < 8; pp++) {
                ffma2(qa, w2f[pp],     sh[pp]);
                ffma2(qa, w2f[8 + pp], xo[pp]);
            }
            const float2 qf = unpack2(qa);
            const float q_new = qf.x + qf.y + br2;
            qA = (a_prev == kA) ? q_new : qA * 0.95f;
            qB = (a_prev == kB) ? q_new : qB * 0.95f;
            atomicAdd(op + (size_t)(NSTEP - 1) * 4,     qA);
            atomicAdd(op + (size_t)(NSTEP - 1) * 4 + 1, qB);
        }
    } else {
        ull w2A[16], w2B[16];                      // rows 2h, 2h+1 (own-first)
        #pragma unroll
        for (int pp = 0; pp < 16; pp++) {
            w2A[pp] = wa2n[h][0][pp];
            w2B[pp] = wa2n[h][1][pp];
        }
        // hoisted weights: m4=0 block, own-half ppo 0..1 (8 ulonglong2)
        ulonglong2 wae[4][2];
        #pragma unroll
        for (int mm = 0; mm < 4; mm++)
            #pragma unroll
            for (int ppo = 0; ppo < 2; ppo++)
                wae[mm][ppo] = wak[mm][h * 4 + ppo][h];
        const float baA = h ? sc[3] : sc[1];
        const float baB = h ? sc[4] : sc[2];

        int a_cur = ap[0];
        for (int t = 0; t < NSTEP; t++) {
            const int a_nxt = ap[(t + 1) * B_SZ];
            ull xo[8];
            #pragma unroll
            for (int u = 0; u < 8; u++) xo[u] = shflx64(sh[u], 1);

            // ---- pipelined epilogue: emit output for step t-1 ----
            if (t > 0) {
                ull cA = 0ull, cB = 0ull;
                #pragma unroll
                for (int pp = 0; pp < 8; pp++) {
                    ffma2(cA, w2A[pp],     sh[pp]);
                    ffma2(cB, w2B[pp],     sh[pp]);
                    ffma2(cA, w2A[8 + pp], xo[pp]);
                    ffma2(cB, w2B[8 + pp], xo[pp]);
                }
                const float2 fA = unpack2(cA), fB = unpack2(cB);
                atomicAdd(op + (size_t)(t - 1) * 4,     fA.x + fA.y + baA);
                atomicAdd(op + (size_t)(t - 1) * 4 + 1, fB.x + fB.y + baB);
            }

            float sn[16];
            #pragma unroll
            for (int m4 = 0; m4 < 4; m4++) {
                const float4 cb = *(const float4*)&colb2[h][m4][a_cur][0];
                ull acc[4];
                #pragma unroll
                for (int mm = 0; mm < 4; mm++) acc[mm] = 0ull;
                #pragma unroll
                for (int ppo = 0; ppo < 4; ppo++) {
                    const int pp = h * 4 + ppo;
                    #pragma unroll
                    for (int mm = 0; mm < 4; mm++) {
                        ulonglong2 w = (m4 == 0 && ppo < 2)
                                     ? wae[mm][ppo]
                                     : wak[m4 * 4 + mm][pp][h];
                        ffma2(acc[mm], w.x, sh[2 * ppo]);
                        ffma2(acc[mm], w.y, sh[2 * ppo + 1]);
                    }
                }
                #pragma unroll
                for (int ppo = 0; ppo < 4; ppo++) {
                    const int pq = (1 - h) * 4 + ppo;
                    #pragma unroll
                    for (int mm = 0; mm < 4; mm++) {
                        ulonglong2 w = wak[m4 * 4 + mm][pq][h];
                        ffma2(acc[mm], w.x, xo[2 * ppo]);
                        ffma2(acc[mm], w.y, xo[2 * ppo + 1]);
                    }
                }
                const float cbv[4] = {cb.x, cb.y, cb.z, cb.w};
                #pragma unroll
                for (int mm = 0; mm < 4; mm++) {
                    float2 u = unpack2(acc[mm]);
                    sn[m4 * 4 + mm] = tanh_pre(u.x + u.y + cbv[mm]);
                }
            }
            #pragma unroll
            for (int u = 0; u < 8; u++) sh[u] = pack2(sn[2 * u], sn[2 * u + 1]);

            a_cur = a_nxt;
        }
        // final epilogue for step NSTEP-1
        {
            ull xo[8];
            #pragma unroll
            for (int u = 0; u < 8; u++) xo[u] = shflx64(sh[u], 1);
            ull cA = 0ull, cB = 0ull;
            #pragma unroll
            for (int pp = 0; pp < 8; pp++) {
                ffma2(cA, w2A[pp],     sh[pp]);
                ffma2(cB, w2B[pp],     sh[pp]);
                ffma2(cA, w2A[8 + pp], xo[pp]);
                ffma2(cB, w2B[8 + pp], xo[pp]);
            }
            const float2 fA = unpack2(cA), fB = unpack2(cB);
            atomicAdd(op + (size_t)(NSTEP - 1) * 4,     fA.x + fA.y + baA);
            atomicAdd(op + (size_t)(NSTEP - 1) * 4 + 1, fB.x + fB.y + baB);
        }
    }
}

extern "C" void kernel_launch(void* const* d_in, const int* in_sizes, int n_in,
                              void* d_out, int out_size) {
    (void)in_sizes; (void)n_in; (void)out_size;
    transpose_kernel<<<dim3(T_LEN / 32, B_SZ / 32, 3), dim3(32, 8)>>>(
        (const int*)d_in[0], (const float*)d_in[1], (float*)d_out);
    memann_mod<<<128, 256>>>(
        (const float*)d_in[2], (const float*)d_in[3],
        (const float*)d_in[4], (const float*)d_in[5],
        (const float*)d_in[6], (const float*)d_in[7],
        (const float*)d_in[8], (const float*)d_in[9],
        (float*)d_out);
}

// round 16
// speedup vs baseline: 2.1492x; 1.0211x over previous
#include <cuda_runtime.h>

#define T_LEN  1024
#define NSTEP  1023
#define B_SZ   8192

typedef unsigned long long ull;

// scratch: time-major inputs
__device__ int   g_act_t[T_LEN * B_SZ];            // [t][b]
__device__ float g_rew_t[T_LEN * B_SZ];            // [t][b]

// ---------------- packed f32x2 helpers ----------------
__device__ __forceinline__ void ffma2(ull& d, ull a, ull b) {
    asm("fma.rn.f32x2 %0, %1, %2, %0;" : "+l"(d) : "l"(a), "l"(b));
}
__device__ __forceinline__ ull mul2(ull a, ull b) {
    ull r; asm("mul.rn.f32x2 %0, %1, %2;" : "=l"(r) : "l"(a), "l"(b)); return r;
}
__device__ __forceinline__ ull pack2(float x, float y) {
    ull r; asm("mov.b64 %0, {%1, %2};" : "=l"(r) : "f"(x), "f"(y)); return r;
}
__device__ __forceinline__ float2 unpack2(ull v) {
    float2 r; asm("mov.b64 {%0, %1}, %2;" : "=f"(r.x), "=f"(r.y) : "l"(v)); return r;
}
__device__ __forceinline__ ull shflx64(ull v, int m) {
    return __shfl_xor_sync(0xFFFFFFFFu, v, m);
}
// input pre-scaled by 2*log2(e):  tanh = 1 - 2/(2^x' + 1)   (~1e-6 abs err)
__device__ __forceinline__ float tanh_pre(float xs) {
    float e, r;
    asm("ex2.approx.f32 %0, %1;" : "=f"(e) : "f"(xs));
    asm("rcp.approx.f32 %0, %1;" : "=f"(r) : "f"(e + 1.0f));
    return fmaf(-2.0f, r, 1.0f);
}
#define TANH_SC 2.8853900817779268f   // 2*log2(e)

// ---------------- transpose [B][T] -> [T][B]  +  zero(out) ----------------
__global__ void __launch_bounds__(256)
transpose_kernel(const int* __restrict__ act, const float* __restrict__ rew,
                 float* __restrict__ out) {
    const int tx = threadIdx.x, ty = threadIdx.y;
    if (blockIdx.z == 2) {
        const size_t base =
            ((size_t)blockIdx.y * gridDim.x + blockIdx.x) * (size_t)NSTEP;
        float4* o4 = (float4*)out;
        const float4 z = make_float4(0.f, 0.f, 0.f, 0.f);
        const int tid = ty * 32 + tx;
        for (int i = tid; i < NSTEP; i += 256) o4[base + i] = z;
        return;
    }
    __shared__ unsigned tile[32][33];
    const int tt = blockIdx.x * 32, tb = blockIdx.y * 32;
    const unsigned* src = (blockIdx.z == 0) ? (const unsigned*)act : (const unsigned*)rew;
    unsigned*       dst = (blockIdx.z == 0) ? (unsigned*)g_act_t  : (unsigned*)g_rew_t;
    #pragma unroll
    for (int i = 0; i < 32; i += 8)
        tile[ty + i][tx] = src[(long long)(tb + ty + i) * T_LEN + tt + tx];
    __syncthreads();
    #pragma unroll
    for (int i = 0; i < 32; i += 8)
        dst[(long long)(tt + ty + i) * B_SZ + tb + tx] = tile[tx][ty + i];
}

// ---------------- main recurrent kernel ----------------
// Champion geometry (128 CTAs x 256 thr; 2 lanes/element; pipelined epilogue;
// RED outputs) + extended LSU wavefront diet: m4=0 own-half weights for
// ppo 0..2 (12 ulonglong2) hoisted to registers in both branches; action
// one-hot bias in compact [h][m4][a][4] layout.
__global__ void __launch_bounds__(256, 1)
memann_mod(const float* __restrict__ w_r1, const float* __restrict__ b_r1,
           const float* __restrict__ w_r2, const float* __restrict__ b_r2,
           const float* __restrict__ w_a1, const float* __restrict__ b_a1,
           const float* __restrict__ w_a2, const float* __restrict__ b_a2,
           float*       __restrict__ out)
{
    __shared__ __align__(16) ulonglong2 wrk[16][8][2];  // [m][pp][h]: row h*16+m
    __shared__ __align__(16) ulonglong2 wak[16][8][2];
    __shared__ __align__(16) ull  bw1s[16][2];          // {b_r1', w_r1[.,0]'}
    __shared__ __align__(16) ull  wr2n[2][16];          // [h][pp]: own-half-first
    __shared__ __align__(16) ull  wa2n[2][2][16];       // [h][k2][pp]: k=2h+k2
    __shared__ __align__(16) float colb2[2][4][4][4];   // [h][m4][a][mm]
    __shared__ float sc[5];                              // b_r2, b_a2[0..3]

    const int tid = threadIdx.x;
    const bool is_reward = blockIdx.x < 64;

    // ---- staging ----
    if (is_reward) {
        #pragma unroll
        for (int k = 0; k < 2; k++) {
            int idx = tid * 2 + k;                 // 512 ull
            int u2 = idx & 1, h = (idx >> 1) & 1, pp = (idx >> 2) & 7, m = idx >> 5;
            int row = h * 16 + m, u = 2 * pp + u2;
            ((ull*)&wrk[m][pp][h])[u2] =
                pack2(w_r1[row * 33 + 1 + 2 * u] * TANH_SC,
                      w_r1[row * 33 + 2 + 2 * u] * TANH_SC);
        }
        if (tid < 32) {
            int h = tid >> 4, m = tid & 15;
            int row = h * 16 + m;
            bw1s[m][h] = pack2(b_r1[row] * TANH_SC, w_r1[row * 33] * TANH_SC);
        }
        if (tid >= 64 && tid < 96) {               // wr2n: own-half-first layout
            int h = (tid - 64) >> 4, pp = (tid - 64) & 15;
            int d = (pp < 8) ? 16 * h + 2 * pp : 16 * (1 - h) + 2 * (pp - 8);
            wr2n[h][pp] = pack2(w_r2[d], w_r2[d + 1]);
        }
        if (tid == 96) sc[0] = b_r2[0];
    } else {
        #pragma unroll
        for (int k = 0; k < 2; k++) {
            int idx = tid * 2 + k;
            int u2 = idx & 1, h = (idx >> 1) & 1, pp = (idx >> 2) & 7, m = idx >> 5;
            int row = h * 16 + m, u = 2 * pp + u2;
            ((ull*)&wak[m][pp][h])[u2] =
                pack2(w_a1[row * 36 + 4 + 2 * u] * TANH_SC,
                      w_a1[row * 36 + 5 + 2 * u] * TANH_SC);
        }
        if (tid < 128) {                           // colb2[h][m4][a][mm]
            int h = tid >> 6, m4 = (tid >> 4) & 3, a = (tid >> 2) & 3, mm = tid & 3;
            int row = h * 16 + m4 * 4 + mm;
            colb2[h][m4][a][mm] = (w_a1[row * 36 + a] + b_a1[row]) * TANH_SC;
        }
        if (tid >= 128 && tid < 192) {             // wa2n: rows k=2h+k2, own-first
            int idx = tid - 128;
            int h = idx >> 5, k2 = (idx >> 4) & 1, pp = idx & 15;
            int kk = 2 * h + k2;
            int d = (pp < 8) ? 16 * h + 2 * pp : 16 * (1 - h) + 2 * (pp - 8);
            wa2n[h][k2][pp] = pack2(w_a2[kk * 32 + d], w_a2[kk * 32 + d + 1]);
        }
        if (tid >= 192 && tid < 196) sc[1 + tid - 192] = b_a2[tid - 192];
    }
    __syncthreads();

    const int lane = tid & 31, wid = tid >> 5;
    const int h  = lane & 1;
    const int el = lane >> 1;
    const int cta_mod = is_reward ? blockIdx.x : blockIdx.x - 64;
    const long long b = (long long)cta_mod * 128 + wid * 16 + el;
    const int*   ap = g_act_t + b;
    const float* rp = g_rew_t + b;

    ull sh[8];
    #pragma unroll
    for (int u = 0; u < 8; u++) sh[u] = 0ull;

    float* op = out + (b * NSTEP) * 4 + 2 * h;   // this lane's 2 output slots

    if (is_reward) {
        ull bi[16];
        #pragma unroll
        for (int m = 0; m < 16; m++) bi[m] = bw1s[m][h];
        ull w2f[16];                               // full w_r2, own-half-first
        #pragma unroll
        for (int pp = 0; pp < 16; pp++) w2f[pp] = wr2n[h][pp];
        // hoisted weights: m4=0 block, own-half ppo 0..2 (12 ulonglong2)
        ulonglong2 wre[4][3];
        #pragma unroll
        for (int mm = 0; mm < 4; mm++)
            #pragma unroll
            for (int ppo = 0; ppo < 3; ppo++)
                wre[mm][ppo] = wrk[mm][h * 4 + ppo][h];
        const float br2 = sc[0];
        const int   kA = 2 * h, kB = 2 * h + 1;
        float qA = 0.f, qB = 0.f;

        int   a_prev = 0;
        int   a_cur  = ap[0];
        float r_cur  = rp[0];
        for (int t = 0; t < NSTEP; t++) {
            const int   a_nxt = ap[(t + 1) * B_SZ];
            const float r_nxt = rp[(t + 1) * B_SZ];
            ull xo[8];
            #pragma unroll
            for (int u = 0; u < 8; u++) xo[u] = shflx64(sh[u], 1);

            // ---- pipelined epilogue: emit output for step t-1 ----
            if (t > 0) {
                ull qa = 0ull;
                #pragma unroll
                for (int pp = 0; pp < 8; pp++) {
                    ffma2(qa, w2f[pp],     sh[pp]);
                    ffma2(qa, w2f[8 + pp], xo[pp]);
                }
                const float2 qf = unpack2(qa);
                const float q_new = qf.x + qf.y + br2;
                qA = (a_prev == kA) ? q_new : qA * 0.95f;
                qB = (a_prev == kB) ? q_new : qB * 0.95f;
                atomicAdd(op + (size_t)(t - 1) * 4,     qA);
                atomicAdd(op + (size_t)(t - 1) * 4 + 1, qB);
            }

            const ull rv = pack2(1.0f, r_cur);
            float sn[16];
            #pragma unroll
            for (int m4 = 0; m4 < 4; m4++) {
                ull acc[4];
                #pragma unroll
                for (int mm = 0; mm < 4; mm++)
                    acc[mm] = mul2(bi[m4 * 4 + mm], rv);   // {b', w0'*r}
                #pragma unroll
                for (int ppo = 0; ppo < 4; ppo++) {         // own half first
                    const int pp = h * 4 + ppo;
                    #pragma unroll
                    for (int mm = 0; mm < 4; mm++) {
                        ulonglong2 w = (m4 == 0 && ppo < 3)
                                     ? wre[mm][ppo]
                                     : wrk[m4 * 4 + mm][pp][h];
                        ffma2(acc[mm], w.x, sh[2 * ppo]);
                        ffma2(acc[mm], w.y, sh[2 * ppo + 1]);
                    }
                }
                #pragma unroll
                for (int ppo = 0; ppo < 4; ppo++) {         // partner half
                    const int pq = (1 - h) * 4 + ppo;
                    #pragma unroll
                    for (int mm = 0; mm < 4; mm++) {
                        ulonglong2 w = wrk[m4 * 4 + mm][pq][h];
                        ffma2(acc[mm], w.x, xo[2 * ppo]);
                        ffma2(acc[mm], w.y, xo[2 * ppo + 1]);
                    }
                }
                #pragma unroll
                for (int mm = 0; mm < 4; mm++) {
                    float2 u = unpack2(acc[mm]);
                    sn[m4 * 4 + mm] = tanh_pre(u.x + u.y);
                }
            }
            #pragma unroll
            for (int u = 0; u < 8; u++) sh[u] = pack2(sn[2 * u], sn[2 * u + 1]);

            a_prev = a_cur; a_cur = a_nxt; r_cur = r_nxt;
        }
        // final epilogue for step NSTEP-1
        {
            ull xo[8];
            #pragma unroll
            for (int u = 0; u < 8; u++) xo[u] = shflx64(sh[u], 1);
            ull qa = 0ull;
            #pragma unroll
            for (int pp = 0; pp < 8; pp++) {
                ffma2(qa, w2f[pp],     sh[pp]);
                ffma2(qa, w2f[8 + pp], xo[pp]);
            }
            const float2 qf = unpack2(qa);
            const float q_new = qf.x + qf.y + br2;
            qA = (a_prev == kA) ? q_new : qA * 0.95f;
            qB = (a_prev == kB) ? q_new : qB * 0.95f;
            atomicAdd(op + (size_t)(NSTEP - 1) * 4,     qA);
            atomicAdd(op + (size_t)(NSTEP - 1) * 4 + 1, qB);
        }
    } else {
        ull w2A[16], w2B[16];                      // rows 2h, 2h+1 (own-first)
        #pragma unroll
        for (int pp = 0; pp < 16; pp++) {
            w2A[pp] = wa2n[h][0][pp];
            w2B[pp] = wa2n[h][1][pp];
        }
        // hoisted weights: m4=0 block, own-half ppo 0..2 (12 ulonglong2)
        ulonglong2 wae[4][3];
        #pragma unroll
        for (int mm = 0; mm < 4; mm++)
            #pragma unroll
            for (int ppo = 0; ppo < 3; ppo++)
                wae[mm][ppo] = wak[mm][h * 4 + ppo][h];
        const float baA = h ? sc[3] : sc[1];
        const float baB = h ? sc[4] : sc[2];

        int a_cur = ap[0];
        for (int t = 0; t < NSTEP; t++) {
            const int a_nxt = ap[(t + 1) * B_SZ];
            ull xo[8];
            #pragma unroll
            for (int u = 0; u < 8; u++) xo[u] = shflx64(sh[u], 1);

            // ---- pipelined epilogue: emit output for step t-1 ----
            if (t > 0) {
                ull cA = 0ull, cB = 0ull;
                #pragma unroll
                for (int pp = 0; pp < 8; pp++) {
                    ffma2(cA, w2A[pp],     sh[pp]);
                    ffma2(cB, w2B[pp],     sh[pp]);
                    ffma2(cA, w2A[8 + pp], xo[pp]);
                    ffma2(cB, w2B[8 + pp], xo[pp]);
                }
                const float2 fA = unpack2(cA), fB = unpack2(cB);
                atomicAdd(op + (size_t)(t - 1) * 4,     fA.x + fA.y + baA);
                atomicAdd(op + (size_t)(t - 1) * 4 + 1, fB.x + fB.y + baB);
            }

            float sn[16];
            #pragma unroll
            for (int m4 = 0; m4 < 4; m4++) {
                const float4 cb = *(const float4*)&colb2[h][m4][a_cur][0];
                ull acc[4];
                #pragma unroll
                for (int mm = 0; mm < 4; mm++) acc[mm] = 0ull;
                #pragma unroll
                for (int ppo = 0; ppo < 4; ppo++) {
                    const int pp = h * 4 + ppo;
                    #pragma unroll
                    for (int mm = 0; mm < 4; mm++) {
                        ulonglong2 w = (m4 == 0 && ppo < 3)
                                     ? wae[mm][ppo]
                                     : wak[m4 * 4 + mm][pp][h];
                        ffma2(acc[mm], w.x, sh[2 * ppo]);
                        ffma2(acc[mm], w.y, sh[2 * ppo + 1]);
                    }
                }
                #pragma unroll
                for (int ppo = 0; ppo < 4; ppo++) {
                    const int pq = (1 - h) * 4 + ppo;
                    #pragma unroll
                    for (int mm = 0; mm < 4; mm++) {
                        ulonglong2 w = wak[m4 * 4 + mm][pq][h];
                        ffma2(acc[mm], w.x, xo[2 * ppo]);
                        ffma2(acc[mm], w.y, xo[2 * ppo + 1]);
                    }
                }
                const float cbv[4] = {cb.x, cb.y, cb.z, cb.w};
                #pragma unroll
                for (int mm = 0; mm < 4; mm++) {
                    float2 u = unpack2(acc[mm]);
                    sn[m4 * 4 + mm] = tanh_pre(u.x + u.y + cbv[mm]);
                }
            }
            #pragma unroll
            for (int u = 0; u < 8; u++) sh[u] = pack2(sn[2 * u], sn[2 * u + 1]);

            a_cur = a_nxt;
        }
        // final epilogue for step NSTEP-1
        {
            ull xo[8];
            #pragma unroll
            for (int u = 0; u < 8; u++) xo[u] = shflx64(sh[u], 1);
            ull cA = 0ull, cB = 0ull;
            #pragma unroll
            for (int pp = 0; pp < 8; pp++) {
                ffma2(cA, w2A[pp],     sh[pp]);
                ffma2(cB, w2B[pp],     sh[pp]);
                ffma2(cA, w2A[8 + pp], xo[pp]);
                ffma2(cB, w2B[8 + pp], xo[pp]);
            }
            const float2 fA = unpack2(cA), fB = unpack2(cB);
            atomicAdd(op + (size_t)(NSTEP - 1) * 4,     fA.x + fA.y + baA);
            atomicAdd(op + (size_t)(NSTEP - 1) * 4 + 1, fB.x + fB.y + baB);
        }
    }
}

extern "C" void kernel_launch(void* const* d_in, const int* in_sizes, int n_in,
                              void* d_out, int out_size) {
    (void)in_sizes; (void)n_in; (void)out_size;
    transpose_kernel<<<dim3(T_LEN / 32, B_SZ / 32, 3), dim3(32, 8)>>>(
        (const int*)d_in[0], (const float*)d_in[1], (float*)d_out);
    memann_mod<<<128, 256>>>(
        (const float*)d_in[2], (const float*)d_in[3],
        (const float*)d_in[4], (const float*)d_in[5],
        (const float*)d_in[6], (const float*)d_in[7],
        (const float*)d_in[8], (const float*)d_in[9],
        (float*)d_out);
}

// round 17
// speedup vs baseline: 2.1646x; 1.0071x over previous
#include <cuda_runtime.h>

#define T_LEN  1024
#define NSTEP  1023
#define B_SZ   8192

typedef unsigned long long ull;

// scratch: time-major inputs
__device__ int   g_act_t[T_LEN * B_SZ];            // [t][b]
__device__ float g_rew_t[T_LEN * B_SZ];            // [t][b]

// ---------------- packed f32x2 helpers ----------------
__device__ __forceinline__ void ffma2(ull& d, ull a, ull b) {
    asm("fma.rn.f32x2 %0, %1, %2, %0;" : "+l"(d) : "l"(a), "l"(b));
}
__device__ __forceinline__ ull mul2(ull a, ull b) {
    ull r; asm("mul.rn.f32x2 %0, %1, %2;" : "=l"(r) : "l"(a), "l"(b)); return r;
}
__device__ __forceinline__ ull pack2(float x, float y) {
    ull r; asm("mov.b64 %0, {%1, %2};" : "=l"(r) : "f"(x), "f"(y)); return r;
}
__device__ __forceinline__ float2 unpack2(ull v) {
    float2 r; asm("mov.b64 {%0, %1}, %2;" : "=f"(r.x), "=f"(r.y) : "l"(v)); return r;
}
__device__ __forceinline__ ull shflx64(ull v, int m) {
    return __shfl_xor_sync(0xFFFFFFFFu, v, m);
}
// input pre-scaled by 2*log2(e):  tanh = 1 - 2/(2^x' + 1)   (~1e-6 abs err)
__device__ __forceinline__ float tanh_pre(float xs) {
    float e, r;
    asm("ex2.approx.f32 %0, %1;" : "=f"(e) : "f"(xs));
    asm("rcp.approx.f32 %0, %1;" : "=f"(r) : "f"(e + 1.0f));
    return fmaf(-2.0f, r, 1.0f);
}
#define TANH_SC 2.8853900817779268f   // 2*log2(e)

// ---------------- transpose [B][T] -> [T][B]  +  zero(out) ----------------
__global__ void __launch_bounds__(256)
transpose_kernel(const int* __restrict__ act, const float* __restrict__ rew,
                 float* __restrict__ out) {
    const int tx = threadIdx.x, ty = threadIdx.y;
    if (blockIdx.z == 2) {
        const size_t base =
            ((size_t)blockIdx.y * gridDim.x + blockIdx.x) * (size_t)NSTEP;
        float4* o4 = (float4*)out;
        const float4 z = make_float4(0.f, 0.f, 0.f, 0.f);
        const int tid = ty * 32 + tx;
        for (int i = tid; i < NSTEP; i += 256) o4[base + i] = z;
        return;
    }
    __shared__ unsigned tile[32][33];
    const int tt = blockIdx.x * 32, tb = blockIdx.y * 32;
    const unsigned* src = (blockIdx.z == 0) ? (const unsigned*)act : (const unsigned*)rew;
    unsigned*       dst = (blockIdx.z == 0) ? (unsigned*)g_act_t  : (unsigned*)g_rew_t;
    #pragma unroll
    for (int i = 0; i < 32; i += 8)
        tile[ty + i][tx] = src[(long long)(tb + ty + i) * T_LEN + tt + tx];
    __syncthreads();
    #pragma unroll
    for (int i = 0; i < 32; i += 8)
        dst[(long long)(tt + ty + i) * B_SZ + tb + tx] = tile[tx][ty + i];
}

// ---------------- main recurrent kernel ----------------
// Champion geometry (128 CTAs x 256 thr; 2 lanes/element; pipelined epilogue;
// RED outputs) + max LSU wavefront diet: m4=0 own-half weights for
// (ppo<3 all mm) plus (ppo=3, mm<2) — 14 ulonglong2 — hoisted to registers in
// both branches; action one-hot bias in compact [h][m4][a][4] layout.
__global__ void __launch_bounds__(256, 1)
memann_mod(const float* __restrict__ w_r1, const float* __restrict__ b_r1,
           const float* __restrict__ w_r2, const float* __restrict__ b_r2,
           const float* __restrict__ w_a1, const float* __restrict__ b_a1,
           const float* __restrict__ w_a2, const float* __restrict__ b_a2,
           float*       __restrict__ out)
{
    __shared__ __align__(16) ulonglong2 wrk[16][8][2];  // [m][pp][h]: row h*16+m
    __shared__ __align__(16) ulonglong2 wak[16][8][2];
    __shared__ __align__(16) ull  bw1s[16][2];          // {b_r1', w_r1[.,0]'}
    __shared__ __align__(16) ull  wr2n[2][16];          // [h][pp]: own-half-first
    __shared__ __align__(16) ull  wa2n[2][2][16];       // [h][k2][pp]: k=2h+k2
    __shared__ __align__(16) float colb2[2][4][4][4];   // [h][m4][a][mm]
    __shared__ float sc[5];                              // b_r2, b_a2[0..3]

    const int tid = threadIdx.x;
    const bool is_reward = blockIdx.x < 64;

    // ---- staging ----
    if (is_reward) {
        #pragma unroll
        for (int k = 0; k < 2; k++) {
            int idx = tid * 2 + k;                 // 512 ull
            int u2 = idx & 1, h = (idx >> 1) & 1, pp = (idx >> 2) & 7, m = idx >> 5;
            int row = h * 16 + m, u = 2 * pp + u2;
            ((ull*)&wrk[m][pp][h])[u2] =
                pack2(w_r1[row * 33 + 1 + 2 * u] * TANH_SC,
                      w_r1[row * 33 + 2 + 2 * u] * TANH_SC);
        }
        if (tid < 32) {
            int h = tid >> 4, m = tid & 15;
            int row = h * 16 + m;
            bw1s[m][h] = pack2(b_r1[row] * TANH_SC, w_r1[row * 33] * TANH_SC);
        }
        if (tid >= 64 && tid < 96) {               // wr2n: own-half-first layout
            int h = (tid - 64) >> 4, pp = (tid - 64) & 15;
            int d = (pp < 8) ? 16 * h + 2 * pp : 16 * (1 - h) + 2 * (pp - 8);
            wr2n[h][pp] = pack2(w_r2[d], w_r2[d + 1]);
        }
        if (tid == 96) sc[0] = b_r2[0];
    } else {
        #pragma unroll
        for (int k = 0; k < 2; k++) {
            int idx = tid * 2 + k;
            int u2 = idx & 1, h = (idx >> 1) & 1, pp = (idx >> 2) & 7, m = idx >> 5;
            int row = h * 16 + m, u = 2 * pp + u2;
            ((ull*)&wak[m][pp][h])[u2] =
                pack2(w_a1[row * 36 + 4 + 2 * u] * TANH_SC,
                      w_a1[row * 36 + 5 + 2 * u] * TANH_SC);
        }
        if (tid < 128) {                           // colb2[h][m4][a][mm]
            int h = tid >> 6, m4 = (tid >> 4) & 3, a = (tid >> 2) & 3, mm = tid & 3;
            int row = h * 16 + m4 * 4 + mm;
            colb2[h][m4][a][mm] = (w_a1[row * 36 + a] + b_a1[row]) * TANH_SC;
        }
        if (tid >= 128 && tid < 192) {             // wa2n: rows k=2h+k2, own-first
            int idx = tid - 128;
            int h = idx >> 5, k2 = (idx >> 4) & 1, pp = idx & 15;
            int kk = 2 * h + k2;
            int d = (pp < 8) ? 16 * h + 2 * pp : 16 * (1 - h) + 2 * (pp - 8);
            wa2n[h][k2][pp] = pack2(w_a2[kk * 32 + d], w_a2[kk * 32 + d + 1]);
        }
        if (tid >= 192 && tid < 196) sc[1 + tid - 192] = b_a2[tid - 192];
    }
    __syncthreads();

    const int lane = tid & 31, wid = tid >> 5;
    const int h  = lane & 1;
    const int el = lane >> 1;
    const int cta_mod = is_reward ? blockIdx.x : blockIdx.x - 64;
    const long long b = (long long)cta_mod * 128 + wid * 16 + el;
    const int*   ap = g_act_t + b;
    const float* rp = g_rew_t + b;

    ull sh[8];
    #pragma unroll
    for (int u = 0; u < 8; u++) sh[u] = 0ull;

    float* op = out + (b * NSTEP) * 4 + 2 * h;   // this lane's 2 output slots

    if (is_reward) {
        ull bi[16];
        #pragma unroll
        for (int m = 0; m < 16; m++) bi[m] = bw1s[m][h];
        ull w2f[16];                               // full w_r2, own-half-first
        #pragma unroll
        for (int pp = 0; pp < 16; pp++) w2f[pp] = wr2n[h][pp];
        // hoisted weights: m4=0 own-half, (ppo<3 all mm) + (ppo=3, mm<2)
        ulonglong2 wre[4][3];
        #pragma unroll
        for (int mm = 0; mm < 4; mm++)
            #pragma unroll
            for (int ppo = 0; ppo < 3; ppo++)
                wre[mm][ppo] = wrk[mm][h * 4 + ppo][h];
        ulonglong2 wre3[2];
        #pragma unroll
        for (int mm = 0; mm < 2; mm++)
            wre3[mm] = wrk[mm][h * 4 + 3][h];
        const float br2 = sc[0];
        const int   kA = 2 * h, kB = 2 * h + 1;
        float qA = 0.f, qB = 0.f;

        int   a_prev = 0;
        int   a_cur  = ap[0];
        float r_cur  = rp[0];
        for (int t = 0; t < NSTEP; t++) {
            const int   a_nxt = ap[(t + 1) * B_SZ];
            const float r_nxt = rp[(t + 1) * B_SZ];
            ull xo[8];
            #pragma unroll
            for (int u = 0; u < 8; u++) xo[u] = shflx64(sh[u], 1);

            // ---- pipelined epilogue: emit output for step t-1 ----
            if (t > 0) {
                ull qa = 0ull;
                #pragma unroll
                for (int pp = 0; pp < 8; pp++) {
                    ffma2(qa, w2f[pp],     sh[pp]);
                    ffma2(qa, w2f[8 + pp], xo[pp]);
                }
                const float2 qf = unpack2(qa);
                const float q_new = qf.x + qf.y + br2;
                qA = (a_prev == kA) ? q_new : qA * 0.95f;
                qB = (a_prev == kB) ? q_new : qB * 0.95f;
                atomicAdd(op + (size_t)(t - 1) * 4,     qA);
                atomicAdd(op + (size_t)(t - 1) * 4 + 1, qB);
            }

            const ull rv = pack2(1.0f, r_cur);
            float sn[16];
            #pragma unroll
            for (int m4 = 0; m4 < 4; m4++) {
                ull acc[4];
                #pragma unroll
                for (int mm = 0; mm < 4; mm++)
                    acc[mm] = mul2(bi[m4 * 4 + mm], rv);   // {b', w0'*r}
                #pragma unroll
                for (int ppo = 0; ppo < 4; ppo++) {         // own half first
                    const int pp = h * 4 + ppo;
                    #pragma unroll
                    for (int mm = 0; mm < 4; mm++) {
                        ulonglong2 w = (m4 == 0 && ppo < 3)
                                     ? wre[mm][ppo]
                                     : ((m4 == 0 && ppo == 3 && mm < 2)
                                        ? wre3[mm]
                                        : wrk[m4 * 4 + mm][pp][h]);
                        ffma2(acc[mm], w.x, sh[2 * ppo]);
                        ffma2(acc[mm], w.y, sh[2 * ppo + 1]);
                    }
                }
                #pragma unroll
                for (int ppo = 0; ppo < 4; ppo++) {         // partner half
                    const int pq = (1 - h) * 4 + ppo;
                    #pragma unroll
                    for (int mm = 0; mm < 4; mm++) {
                        ulonglong2 w = wrk[m4 * 4 + mm][pq][h];
                        ffma2(acc[mm], w.x, xo[2 * ppo]);
                        ffma2(acc[mm], w.y, xo[2 * ppo + 1]);
                    }
                }
                #pragma unroll
                for (int mm = 0; mm < 4; mm++) {
                    float2 u = unpack2(acc[mm]);
                    sn[m4 * 4 + mm] = tanh_pre(u.x + u.y);
                }
            }
            #pragma unroll
            for (int u = 0; u < 8; u++) sh[u] = pack2(sn[2 * u], sn[2 * u + 1]);

            a_prev = a_cur; a_cur = a_nxt; r_cur = r_nxt;
        }
        // final epilogue for step NSTEP-1
        {
            ull xo[8];
            #pragma unroll
            for (int u = 0; u < 8; u++) xo[u] = shflx64(sh[u], 1);
            ull qa = 0ull;
            #pragma unroll
            for (int pp = 0; pp < 8; pp++) {
                ffma2(qa, w2f[pp],     sh[pp]);
                ffma2(qa, w2f[8 + pp], xo[pp]);
            }
            const float2 qf = unpack2(qa);
            const float q_new = qf.x + qf.y + br2;
            qA = (a_prev == kA) ? q_new : qA * 0.95f;
            qB = (a_prev == kB) ? q_new : qB * 0.95f;
            atomicAdd(op + (size_t)(NSTEP - 1) * 4,     qA);
            atomicAdd(op + (size_t)(NSTEP - 1) * 4 + 1, qB);
        }
    } else {
        ull w2A[16], w2B[16];                      // rows 2h, 2h+1 (own-first)
        #pragma unroll
        for (int pp = 0; pp < 16; pp++) {
            w2A[pp] = wa2n[h][0][pp];
            w2B[pp] = wa2n[h][1][pp];
        }
        // hoisted weights: m4=0 own-half, (ppo<3 all mm) + (ppo=3, mm<2)
        ulonglong2 wae[4][3];
        #pragma unroll
        for (int mm = 0; mm < 4; mm++)
            #pragma unroll
            for (int ppo = 0; ppo < 3; ppo++)
                wae[mm][ppo] = wak[mm][h * 4 + ppo][h];
        ulonglong2 wae3[2];
        #pragma unroll
        for (int mm = 0; mm < 2; mm++)
            wae3[mm] = wak[mm][h * 4 + 3][h];
        const float baA = h ? sc[3] : sc[1];
        const float baB = h ? sc[4] : sc[2];

        int a_cur = ap[0];
        for (int t = 0; t < NSTEP; t++) {
            const int a_nxt = ap[(t + 1) * B_SZ];
            ull xo[8];
            #pragma unroll
            for (int u = 0; u < 8; u++) xo[u] = shflx64(sh[u], 1);

            // ---- pipelined epilogue: emit output for step t-1 ----
            if (t > 0) {
                ull cA = 0ull, cB = 0ull;
                #pragma unroll
                for (int pp = 0; pp < 8; pp++) {
                    ffma2(cA, w2A[pp],     sh[pp]);
                    ffma2(cB, w2B[pp],     sh[pp]);
                    ffma2(cA, w2A[8 + pp], xo[pp]);
                    ffma2(cB, w2B[8 + pp], xo[pp]);
                }
                const float2 fA = unpack2(cA), fB = unpack2(cB);
                atomicAdd(op + (size_t)(t - 1) * 4,     fA.x + fA.y + baA);
                atomicAdd(op + (size_t)(t - 1) * 4 + 1, fB.x + fB.y + baB);
            }

            float sn[16];
            #pragma unroll
            for (int m4 = 0; m4 < 4; m4++) {
                const float4 cb = *(const float4*)&colb2[h][m4][a_cur][0];
                ull acc[4];
                #pragma unroll
                for (int mm = 0; mm < 4; mm++) acc[mm] = 0ull;
                #pragma unroll
                for (int ppo = 0; ppo < 4; ppo++) {
                    const int pp = h * 4 + ppo;
                    #pragma unroll
                    for (int mm = 0; mm < 4; mm++) {
                        ulonglong2 w = (m4 == 0 && ppo < 3)
                                     ? wae[mm][ppo]
                                     : ((m4 == 0 && ppo == 3 && mm < 2)
                                        ? wae3[mm]
                                        : wak[m4 * 4 + mm][pp][h]);
                        ffma2(acc[mm], w.x, sh[2 * ppo]);
                        ffma2(acc[mm], w.y, sh[2 * ppo + 1]);
                    }
                }
                #pragma unroll
                for (int ppo = 0; ppo < 4; ppo++) {
                    const int pq = (1 - h) * 4 + ppo;
                    #pragma unroll
                    for (int mm = 0; mm < 4; mm++) {
                        ulonglong2 w = wak[m4 * 4 + mm][pq][h];
                        ffma2(acc[mm], w.x, xo[2 * ppo]);
                        ffma2(acc[mm], w.y, xo[2 * ppo + 1]);
                    }
                }
                const float cbv[4] = {cb.x, cb.y, cb.z, cb.w};
                #pragma unroll
                for (int mm = 0; mm < 4; mm++) {
                    float2 u = unpack2(acc[mm]);
                    sn[m4 * 4 + mm] = tanh_pre(u.x + u.y + cbv[mm]);
                }
            }
            #pragma unroll
            for (int u = 0; u < 8; u++) sh[u] = pack2(sn[2 * u], sn[2 * u + 1]);

            a_cur = a_nxt;
        }
        // final epilogue for step NSTEP-1
        {
            ull xo[8];
            #pragma unroll
            for (int u = 0; u < 8; u++) xo[u] = shflx64(sh[u], 1);
            ull cA = 0ull, cB = 0ull;
            #pragma unroll
            for (int pp = 0; pp < 8; pp++) {
                ffma2(cA, w2A[pp],     sh[pp]);
                ffma2(cB, w2B[pp],     sh[pp]);
                ffma2(cA, w2A[8 + pp], xo[pp]);
                ffma2(cB, w2B[8 + pp], xo[pp]);
            }
            const float2 fA = unpack2(cA), fB = unpack2(cB);
            atomicAdd(op + (size_t)(NSTEP - 1) * 4,     fA.x + fA.y + baA);
            atomicAdd(op + (size_t)(NSTEP - 1) * 4 + 1, fB.x + fB.y + baB);
        }
    }
}

extern "C" void kernel_launch(void* const* d_in, const int* in_sizes, int n_in,
                              void* d_out, int out_size) {
    (void)in_sizes; (void)n_in; (void)out_size;
    transpose_kernel<<<dim3(T_LEN / 32, B_SZ / 32, 3), dim3(32, 8)>>>(
        (const int*)d_in[0], (const float*)d_in[1], (float*)d_out);
    memann_mod<<<128, 256>>>(
        (const float*)d_in[2], (const float*)d_in[3],
        (const float*)d_in[4], (const float*)d_in[5],
        (const float*)d_in[6], (const float*)d_in[7],
        (const float*)d_in[8], (const float*)d_in[9],
        (float*)d_out);
}